// round 11
// baseline (speedup 1.0000x reference)
#include <cuda_runtime.h>
#include <cuda_bf16.h>
#include <mma.h>
#include <cstdint>

using namespace nvcuda;

// Problem constants
#define B       4
#define NSEQ    4096
#define DIM     1024
#define HEADS   8
#define DH      64
#define INNER   512          // HEADS*DH
#define M_ROWS  (B*NSEQ)     // 16384
#define N_QKV   (3*INNER)    // 1536
#define NCHUNK  8
#define ROWS_PER_CHUNK (NSEQ/NCHUNK)  // 512

// Scratch (device globals; no allocation allowed)
__device__ float g_qkv  [(size_t)M_ROWS * N_QKV];     // ~100.7 MB
__device__ float g_ctxp [NCHUNK * B*HEADS * DH * DH]; // 4 MB
__device__ float g_attn [(size_t)M_ROWS * INNER];     // ~33.5 MB (tf32-rounded)
__device__ float g_xc   [(size_t)M_ROWS * DIM];       // 64 MB  (tf32-rounded x)
__device__ float g_wqkvc[(size_t)N_QKV * DIM];        // 6 MB
__device__ float g_woutc[(size_t)DIM * INNER];        // 2 MB

// ---------------------------------------------------------------------------
__device__ __forceinline__ float to_tf32(float x) {
    uint32_t u;
    asm("cvt.rna.tf32.f32 %0, %1;" : "=r"(u) : "f"(x));
    return __uint_as_float(u);
}
__device__ __forceinline__ uint32_t smem_u32(const void* p) {
    uint32_t a;
    asm("{ .reg .u64 t; cvta.to.shared.u64 t, %1; cvt.u32.u64 %0, t; }"
        : "=r"(a) : "l"(p));
    return a;
}
#define CP_ASYNC16(dst, src) \
    asm volatile("cp.async.cg.shared.global [%0], [%1], 16;" \
                 :: "r"(dst), "l"(src) : "memory")
#define CP_COMMIT() asm volatile("cp.async.commit_group;" ::: "memory")
#define CP_WAIT0()  asm volatile("cp.async.wait_group 0;" ::: "memory")
#define CP_WAIT1()  asm volatile("cp.async.wait_group 1;" ::: "memory")

// ---------------------------------------------------------------------------
// Pre-pass: round fp32 -> tf32 (RNA), vectorized
// ---------------------------------------------------------------------------
__global__ __launch_bounds__(256) void cvt_tf32_kernel(
    const float* __restrict__ src, float* __restrict__ dst, int n4)
{
    int i = blockIdx.x * 256 + threadIdx.x;
    if (i < n4) {
        float4 v = ((const float4*)src)[i];
        v.x = to_tf32(v.x); v.y = to_tf32(v.y);
        v.z = to_tf32(v.z); v.w = to_tf32(v.w);
        ((float4*)dst)[i] = v;
    }
}

// ---------------------------------------------------------------------------
// TF32 GEMM (NT): C[M,N] = A[M,K] @ Bm[N,K]^T (+ bias[N])
// Inputs pre-rounded to tf32. CTA tile 128x256, 16 warps (2x8), warp 64x32.
// BK=64, cp.async double-buffered, wmma m16n16k8 tf32.
// Requires M%128==0, N%256==0, K%64==0.
// ---------------------------------------------------------------------------
#define NTHREADS 512
#define BKQ 64                               // K per chunk
#define BKP 72                               // padded K stride (floats)
#define OFF_A0 0
#define OFF_A1 (128*BKP*4)                   // 36864
#define OFF_B0 (2*128*BKP*4)                 // 73728
#define OFF_B1 (OFF_B0 + 256*BKP*4)          // 147456
#define SMEM_GEMM (OFF_B1 + 256*BKP*4)       // 221184 (216 KB)

__global__ __launch_bounds__(NTHREADS) void tf32_gemm_cp(
    const float* __restrict__ A,
    const float* __restrict__ Bm,
    float* __restrict__ C,
    const float* __restrict__ bias,
    int M, int N, int K)
{
    extern __shared__ __align__(16) float smf[];
    const uint32_t sb = smem_u32(smf);
    const int tid = threadIdx.x;
    const int wid = tid >> 5;
    const int bm = blockIdx.y * 128;
    const int bn = blockIdx.x * 256;
    const int wm = (wid >> 3) * 64;          // 0 or 64
    const int wn = (wid & 7) * 32;           // 0..224

    wmma::fragment<wmma::accumulator, 16, 16, 8, float> acc[4][2];
    #pragma unroll
    for (int mi = 0; mi < 4; mi++)
        #pragma unroll
        for (int ni = 0; ni < 2; ni++)
            wmma::fill_fragment(acc[mi][ni], 0.0f);

    // ---- fold bias: acc += ones(0.125) @ biasT (8 k-terms, exact)
    if (bias) {
        float (*biasT)[8] = (float(*)[8])smf;    // 256x8, overlays buffers
        if (tid < 256) {
            float bv = bias[bn + tid];
            #pragma unroll
            for (int k = 0; k < 8; k++) biasT[tid][k] = bv;
        }
        __syncthreads();
        wmma::fragment<wmma::matrix_a, 16, 16, 8, wmma::precision::tf32,
                       wmma::row_major> af;
        wmma::fill_fragment(af, wmma::__float_to_tf32(0.125f));
        #pragma unroll
        for (int ni = 0; ni < 2; ni++) {
            wmma::fragment<wmma::matrix_b, 16, 16, 8, wmma::precision::tf32,
                           wmma::col_major> bf;
            wmma::load_matrix_sync(bf, &biasT[wn + ni * 16][0], 8);
            #pragma unroll
            for (int t = 0; t < bf.num_elements; t++)
                bf.x[t] = wmma::__float_to_tf32(bf.x[t]);
            #pragma unroll
            for (int mi = 0; mi < 4; mi++)
                wmma::mma_sync(acc[mi][ni], af, bf, acc[mi][ni]);
        }
        __syncthreads();
    }

    const float* Aptr = A  + (size_t)bm * K;
    const float* Bptr = Bm + (size_t)bn * K;
    const int nk = K / BKQ;

    // per-thread cp.async coords: 16 float4 per 64-float row
    const int sr = tid >> 4;                  // 0..31
    const int scol = (tid & 15) * 4;          // 0..60

    // issue one chunk's loads into buffer `buf`
    auto issue = [&](int kc, int buf) {
        const float* Ap = Aptr + kc * BKQ;
        const uint32_t abase = sb + (buf ? OFF_A1 : OFF_A0);
        #pragma unroll
        for (int i = 0; i < 4; i++) {
            int r = sr + i * 32;              // 0..127
            CP_ASYNC16(abase + (uint32_t)(r * BKP + scol) * 4,
                       Ap + (size_t)r * K + scol);
        }
        const float* Bp = Bptr + kc * BKQ;
        const uint32_t bbase = sb + (buf ? OFF_B1 : OFF_B0);
        #pragma unroll
        for (int i = 0; i < 8; i++) {
            int r = sr + i * 32;              // 0..255
            CP_ASYNC16(bbase + (uint32_t)(r * BKP + scol) * 4,
                       Bp + (size_t)r * K + scol);
        }
        CP_COMMIT();
    };

    issue(0, 0);

    for (int kc = 0; kc < nk; kc++) {
        const int cur = kc & 1;
        const bool hn = (kc + 1) < nk;
        if (hn) issue(kc + 1, cur ^ 1);
        if (hn) { CP_WAIT1(); } else { CP_WAIT0(); }
        __syncthreads();

        const float* Abuf = smf + (cur ? OFF_A1 : OFF_A0) / 4;
        const float* Bbuf = smf + (cur ? OFF_B1 : OFF_B0) / 4;

        #pragma unroll
        for (int ks = 0; ks < 8; ks++) {
            wmma::fragment<wmma::matrix_a, 16, 16, 8, wmma::precision::tf32,
                           wmma::row_major> af[4];
            wmma::fragment<wmma::matrix_b, 16, 16, 8, wmma::precision::tf32,
                           wmma::col_major> bf[2];
            #pragma unroll
            for (int mi = 0; mi < 4; mi++)
                wmma::load_matrix_sync(af[mi],
                    Abuf + (wm + mi * 16) * BKP + ks * 8, BKP);
            #pragma unroll
            for (int ni = 0; ni < 2; ni++)
                wmma::load_matrix_sync(bf[ni],
                    Bbuf + (wn + ni * 16) * BKP + ks * 8, BKP);
            #pragma unroll
            for (int mi = 0; mi < 4; mi++)
                #pragma unroll
                for (int ni = 0; ni < 2; ni++)
                    wmma::mma_sync(acc[mi][ni], af[mi], bf[ni], acc[mi][ni]);
        }
        __syncthreads();
    }

    #pragma unroll
    for (int mi = 0; mi < 4; mi++)
        #pragma unroll
        for (int ni = 0; ni < 2; ni++)
            wmma::store_matrix_sync(
                &C[(size_t)(bm + wm + mi * 16) * N + bn + wn + ni * 16],
                acc[mi][ni], N, wmma::mem_row_major);
}

// ---------------------------------------------------------------------------
// Context kernel: ctx[d][e] = sum_n softmax(k[n,:])[d] * v[n,e], split-K
// ---------------------------------------------------------------------------
__global__ __launch_bounds__(256) void ctx_kernel()
{
    const int pair  = blockIdx.x;
    const int chunk = blockIdx.y;
    const int b = pair >> 3, h = pair & 7;
    const int tid = threadIdx.x;

    __shared__ __align__(16) float sk[32][DH];
    __shared__ __align__(16) float sv[32][DH];

    const int d0 = (tid >> 4) * 4;
    const int e0 = (tid & 15) * 4;

    float acc[4][4];
    #pragma unroll
    for (int i = 0; i < 4; i++)
        #pragma unroll
        for (int j = 0; j < 4; j++) acc[i][j] = 0.f;

    const float* base = g_qkv + (size_t)b * NSEQ * N_QKV;
    const int n_begin = chunk * ROWS_PER_CHUNK;

    for (int n0 = n_begin; n0 < n_begin + ROWS_PER_CHUNK; n0 += 32) {
        #pragma unroll
        for (int i = 0; i < 2; i++) {
            int id = tid + i * 256;
            int r  = id >> 4;
            int c  = (id & 15) * 4;
            size_t off = (size_t)(n0 + r) * N_QKV + h * DH + c;
            *(float4*)&sk[r][c] = *(const float4*)(base + off + INNER);
            *(float4*)&sv[r][c] = *(const float4*)(base + off + 2 * INNER);
        }
        __syncthreads();

        {
            int r     = tid >> 3;
            int lane8 = tid & 7;
            float vals[8];
            float m = -1e30f;
            #pragma unroll
            for (int j = 0; j < 8; j++) {
                vals[j] = sk[r][lane8 * 8 + j];
                m = fmaxf(m, vals[j]);
            }
            #pragma unroll
            for (int s = 4; s >= 1; s >>= 1)
                m = fmaxf(m, __shfl_xor_sync(0xffffffffu, m, s));
            float sum = 0.f;
            #pragma unroll
            for (int j = 0; j < 8; j++) { vals[j] = __expf(vals[j] - m); sum += vals[j]; }
            #pragma unroll
            for (int s = 4; s >= 1; s >>= 1)
                sum += __shfl_xor_sync(0xffffffffu, sum, s);
            float inv = 1.0f / sum;
            #pragma unroll
            for (int j = 0; j < 8; j++)
                sk[r][lane8 * 8 + j] = vals[j] * inv;
        }
        __syncthreads();

        #pragma unroll 4
        for (int r = 0; r < 32; r++) {
            float4 kd = *(const float4*)&sk[r][d0];
            float4 ve = *(const float4*)&sv[r][e0];
            float kdv[4] = {kd.x, kd.y, kd.z, kd.w};
            float vev[4] = {ve.x, ve.y, ve.z, ve.w};
            #pragma unroll
            for (int i = 0; i < 4; i++)
                #pragma unroll
                for (int j = 0; j < 4; j++)
                    acc[i][j] += kdv[i] * vev[j];
        }
        __syncthreads();
    }

    float* out = g_ctxp + ((size_t)chunk * (B*HEADS) + pair) * DH * DH;
    #pragma unroll
    for (int i = 0; i < 4; i++) {
        float4 v = make_float4(acc[i][0], acc[i][1], acc[i][2], acc[i][3]);
        *(float4*)&out[(d0 + i) * DH + e0] = v;
    }
}

// ---------------------------------------------------------------------------
// Attention-apply; output rounded to tf32 (feeds GEMM4 directly)
// ---------------------------------------------------------------------------
__global__ __launch_bounds__(256) void attn_kernel()
{
    const int pair = blockIdx.x;
    const int b = pair >> 3, h = pair & 7;
    const int n0 = blockIdx.y * 128;
    const int tid = threadIdx.x;

    __shared__ __align__(16) float sctx[DH][DH];
    __shared__ __align__(16) float sq[128][DH];

    for (int idx = tid; idx < DH * DH; idx += 256) {
        float s = 0.f;
        #pragma unroll
        for (int ch = 0; ch < NCHUNK; ch++)
            s += g_ctxp[((size_t)ch * (B*HEADS) + pair) * DH * DH + idx];
        sctx[idx >> 6][idx & 63] = s;
    }

    const float* qbase = g_qkv + (size_t)b * NSEQ * N_QKV + h * DH;
    #pragma unroll
    for (int i = 0; i < 8; i++) {
        int id = tid + i * 256;
        int r  = id >> 4;
        int c  = (id & 15) * 4;
        *(float4*)&sq[r][c] =
            *(const float4*)(qbase + (size_t)(n0 + r) * N_QKV + c);
    }
    __syncthreads();

    const int e0 = (tid & 15) * 4;
    const int rg = tid >> 4;
    float acc[8][4];
    #pragma unroll
    for (int i = 0; i < 8; i++)
        #pragma unroll
        for (int j = 0; j < 4; j++) acc[i][j] = 0.f;

    #pragma unroll 8
    for (int d = 0; d < DH; d++) {
        float4 c4 = *(const float4*)&sctx[d][e0];
        float cv[4] = {c4.x, c4.y, c4.z, c4.w};
        #pragma unroll
        for (int i = 0; i < 8; i++) {
            float a = sq[rg + 16 * i][d];
            #pragma unroll
            for (int j = 0; j < 4; j++)
                acc[i][j] += a * cv[j];
        }
    }

    float* obase = g_attn + (size_t)(b * NSEQ + n0) * INNER + h * DH;
    #pragma unroll
    for (int i = 0; i < 8; i++) {
        int r = rg + 16 * i;
        float4 v = make_float4(to_tf32(acc[i][0]), to_tf32(acc[i][1]),
                               to_tf32(acc[i][2]), to_tf32(acc[i][3]));
        *(float4*)(obase + (size_t)r * INNER + e0) = v;
    }
}

// ---------------------------------------------------------------------------
extern "C" void kernel_launch(void* const* d_in, const int* in_sizes, int n_in,
                              void* d_out, int out_size)
{
    const float* x     = (const float*)d_in[0];   // [4,4096,1024]
    const float* w_qkv = (const float*)d_in[1];   // [1536,1024]
    const float* w_out = (const float*)d_in[2];   // [1024,512]
    const float* b_out = (const float*)d_in[3];   // [1024]
    float* out = (float*)d_out;                   // [4,4096,1024]

    float *qkv_p, *attn_p, *xc_p, *wqkvc_p, *woutc_p;
    cudaGetSymbolAddress((void**)&qkv_p,   g_qkv);
    cudaGetSymbolAddress((void**)&attn_p,  g_attn);
    cudaGetSymbolAddress((void**)&xc_p,    g_xc);
    cudaGetSymbolAddress((void**)&wqkvc_p, g_wqkvc);
    cudaGetSymbolAddress((void**)&woutc_p, g_woutc);

    cudaFuncSetAttribute(tf32_gemm_cp,
        cudaFuncAttributeMaxDynamicSharedMemorySize, SMEM_GEMM);

    // 0) round inputs to tf32 once (streaming)
    {
        int n4x = M_ROWS * DIM / 4;
        cvt_tf32_kernel<<<(n4x + 255) / 256, 256>>>(x, xc_p, n4x);
        int n4q = N_QKV * DIM / 4;
        cvt_tf32_kernel<<<(n4q + 255) / 256, 256>>>(w_qkv, wqkvc_p, n4q);
        int n4o = DIM * INNER / 4;
        cvt_tf32_kernel<<<(n4o + 255) / 256, 256>>>(w_out, woutc_p, n4o);
    }

    // 1) QKV projection: [16384,1536] = xc @ wqkvc^T
    tf32_gemm_cp<<<dim3(N_QKV / 256, M_ROWS / 128), NTHREADS, SMEM_GEMM>>>(
        xc_p, wqkvc_p, qkv_p, nullptr, M_ROWS, N_QKV, DIM);

    // 2) softmax(k) + context partials
    ctx_kernel<<<dim3(B * HEADS, NCHUNK), 256>>>();

    // 3) q @ context -> attn (tf32-rounded) [16384, 512]
    attn_kernel<<<dim3(B * HEADS, NSEQ / 128), 256>>>();

    // 4) output projection + bias: [16384,1024] = attn @ woutc^T + b_out
    tf32_gemm_cp<<<dim3(DIM / 256, M_ROWS / 128), NTHREADS, SMEM_GEMM>>>(
        attn_p, woutc_p, out, b_out, M_ROWS, DIM, INNER);
}

// round 12
// speedup vs baseline: 2.2363x; 2.2363x over previous
#include <cuda_runtime.h>
#include <cuda_bf16.h>
#include <cstdint>

// Problem constants
#define B       4
#define NSEQ    4096
#define DIM     1024
#define HEADS   8
#define DH      64
#define INNER   512          // HEADS*DH
#define M_ROWS  (B*NSEQ)     // 16384
#define N_QKV   (3*INNER)    // 1536
#define NCHUNK  8
#define ROWS_PER_CHUNK (NSEQ/NCHUNK)  // 512

// Scratch (device globals; no allocation allowed)
__device__ float g_qkv  [(size_t)M_ROWS * N_QKV];     // ~100.7 MB (row-major)
__device__ float g_ctxp [NCHUNK * B*HEADS * DH * DH]; // 4 MB
__device__ float g_attn [(size_t)M_ROWS * INNER];     // A-tiled, tf32
__device__ float g_xc   [(size_t)M_ROWS * DIM];       // A-tiled, tf32
__device__ float g_wqkvc[(size_t)N_QKV * DIM];        // B-tiled, tf32
__device__ float g_woutc[(size_t)DIM * INNER];        // B-tiled, tf32

// ---------------------------------------------------------------------------
__device__ __forceinline__ float to_tf32(float x) {
    uint32_t u;
    asm("cvt.rna.tf32.f32 %0, %1;" : "=r"(u) : "f"(x));
    return __uint_as_float(u);
}
__device__ __forceinline__ uint32_t smem_u32(const void* p) {
    uint32_t a;
    asm("{ .reg .u64 t; cvta.to.shared.u64 t, %1; cvt.u32.u64 %0, t; }"
        : "=r"(a) : "l"(p));
    return a;
}
#define CP_ASYNC16(dst, src) \
    asm volatile("cp.async.cg.shared.global [%0], [%1], 16;" \
                 :: "r"(dst), "l"(src) : "memory")
#define CP_COMMIT() asm volatile("cp.async.commit_group;" ::: "memory")
#define CP_WAIT0()  asm volatile("cp.async.wait_group 0;" ::: "memory")
#define CP_WAIT1()  asm volatile("cp.async.wait_group 1;" ::: "memory")

__device__ __forceinline__ void mma_tf32(
    float& c0, float& c1, float& c2, float& c3,
    uint32_t a0, uint32_t a1, uint32_t a2, uint32_t a3,
    uint32_t b0, uint32_t b1)
{
    asm volatile(
        "mma.sync.aligned.m16n8k8.row.col.f32.tf32.tf32.f32 "
        "{%0,%1,%2,%3}, {%4,%5,%6,%7}, {%8,%9}, {%0,%1,%2,%3};"
        : "+f"(c0), "+f"(c1), "+f"(c2), "+f"(c3)
        : "r"(a0), "r"(a1), "r"(a2), "r"(a3), "r"(b0), "r"(b1));
}

// ---------------------------------------------------------------------------
// Tiled layouts (fragment-native for mma.m16n8k8.tf32):
//  A [M,K]: 16x8 block (R,S) at offset (R*(K/8)+S)*128; lane l owns floats
//    [4l..4l+3] = A[16R+g][8S+t], A[16R+g+8][8S+t], A[16R+g][8S+t+4],
//                 A[16R+g+8][8S+t+4]   (g=l>>2, t=l&3)
//  B [N,K]: 8x8 block (Rn,S) at offset (Rn*(K/8)+S)*64; lane l owns floats
//    [2l..2l+1] = Bm[8Rn+g][8S+t], Bm[8Rn+g][8S+t+4]
// ---------------------------------------------------------------------------
__global__ __launch_bounds__(256) void tile_a_kernel(
    const float* __restrict__ src, float* __restrict__ dst, int Mr, int Kc)
{
    int gid = blockIdx.x * 256 + threadIdx.x;
    int total = (Mr >> 4) * (Kc >> 3) * 32;
    if (gid >= total) return;
    int lane = gid & 31, blk = gid >> 5;
    int SB = Kc >> 3;
    int R = blk / SB, S = blk % SB;
    int g = lane >> 2, t = lane & 3;
    size_t r0 = (size_t)(R * 16 + g) * Kc + S * 8 + t;
    size_t r1 = r0 + (size_t)8 * Kc;
    float4 v;
    v.x = to_tf32(src[r0]);
    v.y = to_tf32(src[r1]);
    v.z = to_tf32(src[r0 + 4]);
    v.w = to_tf32(src[r1 + 4]);
    ((float4*)dst)[gid] = v;
}

__global__ __launch_bounds__(256) void tile_b_kernel(
    const float* __restrict__ src, float* __restrict__ dst, int Nr, int Kc)
{
    int gid = blockIdx.x * 256 + threadIdx.x;
    int total = (Nr >> 3) * (Kc >> 3) * 32;
    if (gid >= total) return;
    int lane = gid & 31, blk = gid >> 5;
    int SB = Kc >> 3;
    int Rn = blk / SB, S = blk % SB;
    int g = lane >> 2, t = lane & 3;
    size_t r0 = (size_t)(Rn * 8 + g) * Kc + S * 8 + t;
    float2 v;
    v.x = to_tf32(src[r0]);
    v.y = to_tf32(src[r0 + 4]);
    ((float2*)dst)[gid] = v;
}

// ---------------------------------------------------------------------------
// TF32 GEMM (NT): C[M,N] = A[M,K] @ Bm[N,K]^T (+ bias[N]), C row-major fp32.
// A in A-tiled layout, Bm in B-tiled layout (both pre-rounded tf32).
// CTA tile 128x256, 8 warps (2x4), warp 64x64. BK=64, cp.async double-buffer.
// ---------------------------------------------------------------------------
#define BKQ 64
#define A_ST_FLT (128*BKQ)                  // 8192 floats / stage
#define B_ST_FLT (256*BKQ)                  // 16384 floats / stage
#define OFF_A0 0
#define OFF_A1 (A_ST_FLT*4)                 // 32768 B
#define OFF_B0 (2*A_ST_FLT*4)               // 65536 B
#define OFF_B1 (OFF_B0 + B_ST_FLT*4)        // 131072 B
#define SMEM_GEMM (OFF_B1 + B_ST_FLT*4)     // 196608 B (192 KB)

__global__ __launch_bounds__(256) void tf32_gemm_mma(
    const float* __restrict__ A,
    const float* __restrict__ Bm,
    float* __restrict__ C,
    const float* __restrict__ bias,
    int M, int N, int K)
{
    extern __shared__ __align__(16) float smf[];
    const uint32_t sb = smem_u32(smf);
    const int tid  = threadIdx.x;
    const int wid  = tid >> 5;
    const int lane = tid & 31;
    const int g = lane >> 2, tg = lane & 3;
    const int bm = blockIdx.y * 128;
    const int bn = blockIdx.x * 256;
    const int wm = (wid >> 2) * 64;          // 0 or 64
    const int wn = (wid & 3) * 64;           // 0..192

    float acc[4][8][4];
    #pragma unroll
    for (int mi = 0; mi < 4; mi++)
        #pragma unroll
        for (int ni = 0; ni < 8; ni++)
            #pragma unroll
            for (int c = 0; c < 4; c++)
                acc[mi][ni][c] = 0.f;

    const int SB = K >> 3;                   // blocks along K
    // A tile for (bm, kc): 8 block-rows, run stride SB*128 floats,
    // each run = 8 blocks * 128 = 1024 contiguous floats.
    const float* Abase0 = A + ((size_t)(bm >> 4) * SB) * 128;
    const size_t AstrR  = (size_t)SB * 128;
    // B tile: 32 n-block runs, stride SB*64, each run 8*64=512 floats.
    const float* Bbase0 = Bm + ((size_t)(bn >> 3) * SB) * 64;
    const size_t BstrR  = (size_t)SB * 64;

    const int nk = K / BKQ;

    auto issue = [&](int kc, int buf) {
        const float* Ab = Abase0 + (size_t)kc * 8 * 128;
        const uint32_t ad = sb + (buf ? OFF_A1 : OFF_A0);
        #pragma unroll
        for (int i = 0; i < 8; i++) {
            int f4  = tid + i * 256;          // 0..2047
            int flt = f4 << 2;
            int run = flt >> 10;              // block-row 0..7
            int win = flt & 1023;
            CP_ASYNC16(ad + (uint32_t)f4 * 16, Ab + (size_t)run * AstrR + win);
        }
        const float* Bb = Bbase0 + (size_t)kc * 8 * 64;
        const uint32_t bd = sb + (buf ? OFF_B1 : OFF_B0);
        #pragma unroll
        for (int i = 0; i < 16; i++) {
            int f4  = tid + i * 256;          // 0..4095
            int flt = f4 << 2;
            int run = flt >> 9;               // n-block 0..31
            int win = flt & 511;
            CP_ASYNC16(bd + (uint32_t)f4 * 16, Bb + (size_t)run * BstrR + win);
        }
        CP_COMMIT();
    };

    issue(0, 0);

    for (int kc = 0; kc < nk; kc++) {
        const int cur = kc & 1;
        const bool hn = (kc + 1) < nk;
        if (hn) issue(kc + 1, cur ^ 1);
        if (hn) { CP_WAIT1(); } else { CP_WAIT0(); }
        __syncthreads();

        const float* As = smf + (cur ? OFF_A1 : OFF_A0) / 4;
        const float* Bs = smf + (cur ? OFF_B1 : OFF_B0) / 4;
        const int abr = wm >> 4;              // first A block-row (0 or 4)
        const int bbr = wn >> 3;              // first B n-block (0..24)

        #pragma unroll
        for (int ks = 0; ks < 8; ks++) {
            uint32_t af[4][4];
            #pragma unroll
            for (int mi = 0; mi < 4; mi++) {
                float4 v = *(const float4*)(
                    As + ((abr + mi) * 8 + ks) * 128 + lane * 4);
                af[mi][0] = __float_as_uint(v.x);
                af[mi][1] = __float_as_uint(v.y);
                af[mi][2] = __float_as_uint(v.z);
                af[mi][3] = __float_as_uint(v.w);
            }
            uint32_t bf[8][2];
            #pragma unroll
            for (int ni = 0; ni < 8; ni++) {
                float2 v = *(const float2*)(
                    Bs + ((bbr + ni) * 8 + ks) * 64 + lane * 2);
                bf[ni][0] = __float_as_uint(v.x);
                bf[ni][1] = __float_as_uint(v.y);
            }
            #pragma unroll
            for (int mi = 0; mi < 4; mi++)
                #pragma unroll
                for (int ni = 0; ni < 8; ni++)
                    mma_tf32(acc[mi][ni][0], acc[mi][ni][1],
                             acc[mi][ni][2], acc[mi][ni][3],
                             af[mi][0], af[mi][1], af[mi][2], af[mi][3],
                             bf[ni][0], bf[ni][1]);
        }
        __syncthreads();
    }

    // epilogue: c0/c1 at (row g, cols 2t,2t+1); c2/c3 at (row g+8)
    #pragma unroll
    for (int ni = 0; ni < 8; ni++) {
        const int col = bn + wn + ni * 8 + tg * 2;
        float b0 = 0.f, b1 = 0.f;
        if (bias) { b0 = bias[col]; b1 = bias[col + 1]; }
        #pragma unroll
        for (int mi = 0; mi < 4; mi++) {
            const int r0 = bm + wm + mi * 16 + g;
            *(float2*)&C[(size_t)r0 * N + col] =
                make_float2(acc[mi][ni][0] + b0, acc[mi][ni][1] + b1);
            *(float2*)&C[(size_t)(r0 + 8) * N + col] =
                make_float2(acc[mi][ni][2] + b0, acc[mi][ni][3] + b1);
        }
    }
}

// ---------------------------------------------------------------------------
// Context kernel: ctx[d][e] = sum_n softmax(k[n,:])[d] * v[n,e], split-K
// (reads row-major g_qkv)
// ---------------------------------------------------------------------------
__global__ __launch_bounds__(256) void ctx_kernel()
{
    const int pair  = blockIdx.x;
    const int chunk = blockIdx.y;
    const int b = pair >> 3, h = pair & 7;
    const int tid = threadIdx.x;

    __shared__ __align__(16) float sk[32][DH];
    __shared__ __align__(16) float sv[32][DH];

    const int d0 = (tid >> 4) * 4;
    const int e0 = (tid & 15) * 4;

    float acc[4][4];
    #pragma unroll
    for (int i = 0; i < 4; i++)
        #pragma unroll
        for (int j = 0; j < 4; j++) acc[i][j] = 0.f;

    const float* base = g_qkv + (size_t)b * NSEQ * N_QKV;
    const int n_begin = chunk * ROWS_PER_CHUNK;

    for (int n0 = n_begin; n0 < n_begin + ROWS_PER_CHUNK; n0 += 32) {
        #pragma unroll
        for (int i = 0; i < 2; i++) {
            int id = tid + i * 256;
            int r  = id >> 4;
            int c  = (id & 15) * 4;
            size_t off = (size_t)(n0 + r) * N_QKV + h * DH + c;
            *(float4*)&sk[r][c] = *(const float4*)(base + off + INNER);
            *(float4*)&sv[r][c] = *(const float4*)(base + off + 2 * INNER);
        }
        __syncthreads();

        {
            int r     = tid >> 3;
            int lane8 = tid & 7;
            float vals[8];
            float m = -1e30f;
            #pragma unroll
            for (int j = 0; j < 8; j++) {
                vals[j] = sk[r][lane8 * 8 + j];
                m = fmaxf(m, vals[j]);
            }
            #pragma unroll
            for (int s = 4; s >= 1; s >>= 1)
                m = fmaxf(m, __shfl_xor_sync(0xffffffffu, m, s));
            float sum = 0.f;
            #pragma unroll
            for (int j = 0; j < 8; j++) { vals[j] = __expf(vals[j] - m); sum += vals[j]; }
            #pragma unroll
            for (int s = 4; s >= 1; s >>= 1)
                sum += __shfl_xor_sync(0xffffffffu, sum, s);
            float inv = 1.0f / sum;
            #pragma unroll
            for (int j = 0; j < 8; j++)
                sk[r][lane8 * 8 + j] = vals[j] * inv;
        }
        __syncthreads();

        #pragma unroll 4
        for (int r = 0; r < 32; r++) {
            float4 kd = *(const float4*)&sk[r][d0];
            float4 ve = *(const float4*)&sv[r][e0];
            float kdv[4] = {kd.x, kd.y, kd.z, kd.w};
            float vev[4] = {ve.x, ve.y, ve.z, ve.w};
            #pragma unroll
            for (int i = 0; i < 4; i++)
                #pragma unroll
                for (int j = 0; j < 4; j++)
                    acc[i][j] += kdv[i] * vev[j];
        }
        __syncthreads();
    }

    float* out = g_ctxp + ((size_t)chunk * (B*HEADS) + pair) * DH * DH;
    #pragma unroll
    for (int i = 0; i < 4; i++) {
        float4 v = make_float4(acc[i][0], acc[i][1], acc[i][2], acc[i][3]);
        *(float4*)&out[(d0 + i) * DH + e0] = v;
    }
}

// ---------------------------------------------------------------------------
// Attention-apply; writes g_attn in A-tiled tf32 layout (feeds GEMM4)
// ---------------------------------------------------------------------------
__global__ __launch_bounds__(256) void attn_kernel()
{
    const int pair = blockIdx.x;
    const int b = pair >> 3, h = pair & 7;
    const int n0 = blockIdx.y * 128;
    const int tid = threadIdx.x;

    __shared__ __align__(16) float sctx[DH][DH];
    __shared__ __align__(16) float sq[128][DH];

    for (int idx = tid; idx < DH * DH; idx += 256) {
        float s = 0.f;
        #pragma unroll
        for (int ch = 0; ch < NCHUNK; ch++)
            s += g_ctxp[((size_t)ch * (B*HEADS) + pair) * DH * DH + idx];
        sctx[idx >> 6][idx & 63] = s;
    }

    const float* qbase = g_qkv + (size_t)b * NSEQ * N_QKV + h * DH;
    #pragma unroll
    for (int i = 0; i < 8; i++) {
        int id = tid + i * 256;
        int r  = id >> 4;
        int c  = (id & 15) * 4;
        *(float4*)&sq[r][c] =
            *(const float4*)(qbase + (size_t)(n0 + r) * N_QKV + c);
    }
    __syncthreads();

    const int e0 = (tid & 15) * 4;
    const int rg = tid >> 4;
    float acc[8][4];
    #pragma unroll
    for (int i = 0; i < 8; i++)
        #pragma unroll
        for (int j = 0; j < 4; j++) acc[i][j] = 0.f;

    #pragma unroll 8
    for (int d = 0; d < DH; d++) {
        float4 c4 = *(const float4*)&sctx[d][e0];
        float cv[4] = {c4.x, c4.y, c4.z, c4.w};
        #pragma unroll
        for (int i = 0; i < 8; i++) {
            float a = sq[rg + 16 * i][d];
            #pragma unroll
            for (int j = 0; j < 4; j++)
                acc[i][j] += a * cv[j];
        }
    }

    // tiled store: row = b*NSEQ + n0 + rg + 16*i, col = h*64 + e0 + j
    const int R0 = (b * NSEQ + n0) >> 4;          // + i
    const int S  = (h * DH + e0) >> 3;
    const int g2 = rg & 7;
    const int slot = (rg >> 3) + ((e0 & 4) ? 2 : 0);
    #pragma unroll
    for (int i = 0; i < 8; i++) {
        float* blk = g_attn + ((size_t)(R0 + i) * (INNER >> 3) + S) * 128;
        #pragma unroll
        for (int j = 0; j < 4; j++)
            blk[(g2 * 4 + j) * 4 + slot] = to_tf32(acc[i][j]);
    }
}

// ---------------------------------------------------------------------------
extern "C" void kernel_launch(void* const* d_in, const int* in_sizes, int n_in,
                              void* d_out, int out_size)
{
    const float* x     = (const float*)d_in[0];   // [4,4096,1024]
    const float* w_qkv = (const float*)d_in[1];   // [1536,1024]
    const float* w_out = (const float*)d_in[2];   // [1024,512]
    const float* b_out = (const float*)d_in[3];   // [1024]
    float* out = (float*)d_out;                   // [4,4096,1024]

    float *qkv_p, *attn_p, *xc_p, *wqkvc_p, *woutc_p;
    cudaGetSymbolAddress((void**)&qkv_p,   g_qkv);
    cudaGetSymbolAddress((void**)&attn_p,  g_attn);
    cudaGetSymbolAddress((void**)&xc_p,    g_xc);
    cudaGetSymbolAddress((void**)&wqkvc_p, g_wqkvc);
    cudaGetSymbolAddress((void**)&woutc_p, g_woutc);

    cudaFuncSetAttribute(tf32_gemm_mma,
        cudaFuncAttributeMaxDynamicSharedMemorySize, SMEM_GEMM);

    // 0) tile + round inputs to fragment-native tf32 layouts
    {
        int ta = (M_ROWS / 16) * (DIM / 8) * 32;
        tile_a_kernel<<<(ta + 255) / 256, 256>>>(x, xc_p, M_ROWS, DIM);
        int tb1 = (N_QKV / 8) * (DIM / 8) * 32;
        tile_b_kernel<<<(tb1 + 255) / 256, 256>>>(w_qkv, wqkvc_p, N_QKV, DIM);
        int tb2 = (DIM / 8) * (INNER / 8) * 32;
        tile_b_kernel<<<(tb2 + 255) / 256, 256>>>(w_out, woutc_p, DIM, INNER);
    }

    // 1) QKV projection: [16384,1536] = xc @ wqkvc^T
    tf32_gemm_mma<<<dim3(N_QKV / 256, M_ROWS / 128), 256, SMEM_GEMM>>>(
        xc_p, wqkvc_p, qkv_p, nullptr, M_ROWS, N_QKV, DIM);

    // 2) softmax(k) + context partials
    ctx_kernel<<<dim3(B * HEADS, NCHUNK), 256>>>();

    // 3) q @ context -> attn (tiled tf32) [16384, 512]
    attn_kernel<<<dim3(B * HEADS, NSEQ / 128), 256>>>();

    // 4) output projection + bias: [16384,1024] = attn @ woutc^T + b_out
    tf32_gemm_mma<<<dim3(DIM / 256, M_ROWS / 128), 256, SMEM_GEMM>>>(
        attn_p, woutc_p, out, b_out, M_ROWS, DIM, INNER);
}

// round 13
// speedup vs baseline: 2.2729x; 1.0164x over previous
#include <cuda_runtime.h>
#include <cuda_bf16.h>
#include <cstdint>

// Problem constants
#define B       4
#define NSEQ    4096
#define DIM     1024
#define HEADS   8
#define DH      64
#define INNER   512          // HEADS*DH
#define M_ROWS  (B*NSEQ)     // 16384
#define N_QKV   (3*INNER)    // 1536
#define NCHUNK  8
#define ROWS_PER_CHUNK (NSEQ/NCHUNK)  // 512

// Scratch (device globals; no allocation allowed)
__device__ float g_qkv  [(size_t)M_ROWS * N_QKV];     // ~100.7 MB (row-major)
__device__ float g_ctxp [NCHUNK * B*HEADS * DH * DH]; // 4 MB
__device__ float g_attn [(size_t)M_ROWS * INNER];     // A-tiled, tf32
__device__ float g_xc   [(size_t)M_ROWS * DIM];       // A-tiled, tf32
__device__ float g_wqkvc[(size_t)N_QKV * DIM];        // B-tiled, tf32
__device__ float g_woutc[(size_t)DIM * INNER];        // B-tiled, tf32

// ---------------------------------------------------------------------------
__device__ __forceinline__ float to_tf32(float x) {
    uint32_t u;
    asm("cvt.rna.tf32.f32 %0, %1;" : "=r"(u) : "f"(x));
    return __uint_as_float(u);
}
__device__ __forceinline__ uint32_t smem_u32(const void* p) {
    uint32_t a;
    asm("{ .reg .u64 t; cvta.to.shared.u64 t, %1; cvt.u32.u64 %0, t; }"
        : "=r"(a) : "l"(p));
    return a;
}
#define CP_ASYNC16(dst, src) \
    asm volatile("cp.async.cg.shared.global [%0], [%1], 16;" \
                 :: "r"(dst), "l"(src) : "memory")
#define CP_COMMIT() asm volatile("cp.async.commit_group;" ::: "memory")
#define CP_WAIT2()  asm volatile("cp.async.wait_group 2;" ::: "memory")

__device__ __forceinline__ void mma_tf32(
    float& c0, float& c1, float& c2, float& c3,
    uint32_t a0, uint32_t a1, uint32_t a2, uint32_t a3,
    uint32_t b0, uint32_t b1)
{
    asm volatile(
        "mma.sync.aligned.m16n8k8.row.col.f32.tf32.tf32.f32 "
        "{%0,%1,%2,%3}, {%4,%5,%6,%7}, {%8,%9}, {%0,%1,%2,%3};"
        : "+f"(c0), "+f"(c1), "+f"(c2), "+f"(c3)
        : "r"(a0), "r"(a1), "r"(a2), "r"(a3), "r"(b0), "r"(b1));
}

// ---------------------------------------------------------------------------
// Tiled layouts (fragment-native for mma.m16n8k8.tf32):
//  A [M,K]: 16x8 block (R,S) at offset (R*(K/8)+S)*128; lane l owns floats
//    [4l..4l+3] = A[16R+g][8S+t], A[16R+g+8][8S+t], A[16R+g][8S+t+4],
//                 A[16R+g+8][8S+t+4]   (g=l>>2, t=l&3)
//  B [N,K]: 8x8 block (Rn,S) at offset (Rn*(K/8)+S)*64; lane l owns floats
//    [2l..2l+1] = Bm[8Rn+g][8S+t], Bm[8Rn+g][8S+t+4]
// ---------------------------------------------------------------------------
__global__ __launch_bounds__(256) void tile_a_kernel(
    const float* __restrict__ src, float* __restrict__ dst, int Mr, int Kc)
{
    int gid = blockIdx.x * 256 + threadIdx.x;
    int total = (Mr >> 4) * (Kc >> 3) * 32;
    if (gid >= total) return;
    int lane = gid & 31, blk = gid >> 5;
    int SB = Kc >> 3;
    int R = blk / SB, S = blk % SB;
    int g = lane >> 2, t = lane & 3;
    size_t r0 = (size_t)(R * 16 + g) * Kc + S * 8 + t;
    size_t r1 = r0 + (size_t)8 * Kc;
    float4 v;
    v.x = to_tf32(src[r0]);
    v.y = to_tf32(src[r1]);
    v.z = to_tf32(src[r0 + 4]);
    v.w = to_tf32(src[r1 + 4]);
    ((float4*)dst)[gid] = v;
}

__global__ __launch_bounds__(256) void tile_b_kernel(
    const float* __restrict__ src, float* __restrict__ dst, int Nr, int Kc)
{
    int gid = blockIdx.x * 256 + threadIdx.x;
    int total = (Nr >> 3) * (Kc >> 3) * 32;
    if (gid >= total) return;
    int lane = gid & 31, blk = gid >> 5;
    int SB = Kc >> 3;
    int Rn = blk / SB, S = blk % SB;
    int g = lane >> 2, t = lane & 3;
    size_t r0 = (size_t)(Rn * 8 + g) * Kc + S * 8 + t;
    float2 v;
    v.x = to_tf32(src[r0]);
    v.y = to_tf32(src[r0 + 4]);
    ((float2*)dst)[gid] = v;
}

// ---------------------------------------------------------------------------
// TF32 GEMM (NT): C[M,N] = A[M,K] @ Bm[N,K]^T (+ bias[N]), C row-major fp32.
// A in A-tiled layout, Bm in B-tiled layout (both pre-rounded tf32).
// CTA tile 128x256, 8 warps (2x4), warp 64x64. BK=32, 4-stage cp.async ring.
// ---------------------------------------------------------------------------
#define BKQ 32
#define NSTAGE 4
#define A_ST_FLT (128*BKQ)                  // 4096 floats / stage (16 KB)
#define B_ST_FLT (256*BKQ)                  // 8192 floats / stage (32 KB)
#define OFF_A(s) ((s) * A_ST_FLT * 4)
#define OFF_B(s) (NSTAGE*A_ST_FLT*4 + (s) * B_ST_FLT * 4)
#define SMEM_GEMM (NSTAGE*(A_ST_FLT+B_ST_FLT)*4)   // 196608 B (192 KB)

__global__ __launch_bounds__(256) void tf32_gemm_mma(
    const float* __restrict__ A,
    const float* __restrict__ Bm,
    float* __restrict__ C,
    const float* __restrict__ bias,
    int M, int N, int K)
{
    extern __shared__ __align__(16) float smf[];
    const uint32_t sb = smem_u32(smf);
    const int tid  = threadIdx.x;
    const int wid  = tid >> 5;
    const int lane = tid & 31;
    const int g = lane >> 2, tg = lane & 3;
    const int bm = blockIdx.y * 128;
    const int bn = blockIdx.x * 256;
    const int wm = (wid >> 2) * 64;          // 0 or 64
    const int wn = (wid & 3) * 64;           // 0..192

    float acc[4][8][4];
    #pragma unroll
    for (int mi = 0; mi < 4; mi++)
        #pragma unroll
        for (int ni = 0; ni < 8; ni++)
            #pragma unroll
            for (int c = 0; c < 4; c++)
                acc[mi][ni][c] = 0.f;

    const int SB = K >> 3;                   // 8-wide k-blocks along K
    const float* Abase0 = A + ((size_t)(bm >> 4) * SB) * 128;
    const size_t AstrR  = (size_t)SB * 128;  // stride between M block-rows
    const float* Bbase0 = Bm + ((size_t)(bn >> 3) * SB) * 64;
    const size_t BstrR  = (size_t)SB * 64;   // stride between N blocks

    const int nk = K / BKQ;                  // chunks (4 k-blocks each)

    // per chunk: A segment per block-row = 4 blocks * 128 = 512 contiguous
    //            B segment per n-block   = 4 blocks * 64  = 256 contiguous
    auto issue = [&](int kc, int buf) {
        const float* Ab = Abase0 + (size_t)kc * 4 * 128;
        const uint32_t ad = sb + OFF_A(buf);
        #pragma unroll
        for (int i = 0; i < 4; i++) {
            int f4  = tid + i * 256;          // 0..1023
            int flt = f4 << 2;
            int run = flt >> 9;               // block-row 0..7
            int win = flt & 511;
            CP_ASYNC16(ad + (uint32_t)f4 * 16, Ab + (size_t)run * AstrR + win);
        }
        const float* Bb = Bbase0 + (size_t)kc * 4 * 64;
        const uint32_t bd = sb + OFF_B(buf);
        #pragma unroll
        for (int i = 0; i < 8; i++) {
            int f4  = tid + i * 256;          // 0..2047
            int flt = f4 << 2;
            int run = flt >> 8;               // n-block 0..31
            int win = flt & 255;
            CP_ASYNC16(bd + (uint32_t)f4 * 16, Bb + (size_t)run * BstrR + win);
        }
        CP_COMMIT();
    };

    // prologue: 3 stages in flight
    issue(0, 0);
    if (nk > 1) issue(1, 1); else CP_COMMIT();
    if (nk > 2) issue(2, 2); else CP_COMMIT();

    const int abr = wm >> 4;                  // first A block-row (0 or 4)
    const int bbr = wn >> 3;                  // first B n-block (0..24)

    for (int kc = 0; kc < nk; kc++) {
        // stage kc's group has exactly 2 newer groups committed -> wait 2
        CP_WAIT2();
        __syncthreads();

        const int cur = kc & (NSTAGE - 1);
        const float* As = smf + OFF_A(cur) / 4;
        const float* Bs = smf + OFF_B(cur) / 4;

        #pragma unroll
        for (int ks = 0; ks < 4; ks++) {
            uint32_t af[4][4];
            #pragma unroll
            for (int mi = 0; mi < 4; mi++) {
                float4 v = *(const float4*)(
                    As + ((abr + mi) * 4 + ks) * 128 + lane * 4);
                af[mi][0] = __float_as_uint(v.x);
                af[mi][1] = __float_as_uint(v.y);
                af[mi][2] = __float_as_uint(v.z);
                af[mi][3] = __float_as_uint(v.w);
            }
            uint32_t bf[8][2];
            #pragma unroll
            for (int ni = 0; ni < 8; ni++) {
                float2 v = *(const float2*)(
                    Bs + ((bbr + ni) * 4 + ks) * 64 + lane * 2);
                bf[ni][0] = __float_as_uint(v.x);
                bf[ni][1] = __float_as_uint(v.y);
            }
            #pragma unroll
            for (int mi = 0; mi < 4; mi++)
                #pragma unroll
                for (int ni = 0; ni < 8; ni++)
                    mma_tf32(acc[mi][ni][0], acc[mi][ni][1],
                             acc[mi][ni][2], acc[mi][ni][3],
                             af[mi][0], af[mi][1], af[mi][2], af[mi][3],
                             bf[ni][0], bf[ni][1]);
        }

        // produce stage kc+3 (slot == (kc-1)%4; all warps left it at barrier)
        if (kc + 3 < nk) issue(kc + 3, (kc + 3) & (NSTAGE - 1));
        else CP_COMMIT();                      // keep group accounting uniform
    }

    // epilogue: c0/c1 at (row g, cols 2t,2t+1); c2/c3 at (row g+8)
    #pragma unroll
    for (int ni = 0; ni < 8; ni++) {
        const int col = bn + wn + ni * 8 + tg * 2;
        float b0 = 0.f, b1 = 0.f;
        if (bias) { b0 = bias[col]; b1 = bias[col + 1]; }
        #pragma unroll
        for (int mi = 0; mi < 4; mi++) {
            const int r0 = bm + wm + mi * 16 + g;
            *(float2*)&C[(size_t)r0 * N + col] =
                make_float2(acc[mi][ni][0] + b0, acc[mi][ni][1] + b1);
            *(float2*)&C[(size_t)(r0 + 8) * N + col] =
                make_float2(acc[mi][ni][2] + b0, acc[mi][ni][3] + b1);
        }
    }
}

// ---------------------------------------------------------------------------
// Context kernel: ctx[d][e] = sum_n softmax(k[n,:])[d] * v[n,e], split-K
// ---------------------------------------------------------------------------
__global__ __launch_bounds__(256) void ctx_kernel()
{
    const int pair  = blockIdx.x;
    const int chunk = blockIdx.y;
    const int b = pair >> 3, h = pair & 7;
    const int tid = threadIdx.x;

    __shared__ __align__(16) float sk[32][DH];
    __shared__ __align__(16) float sv[32][DH];

    const int d0 = (tid >> 4) * 4;
    const int e0 = (tid & 15) * 4;

    float acc[4][4];
    #pragma unroll
    for (int i = 0; i < 4; i++)
        #pragma unroll
        for (int j = 0; j < 4; j++) acc[i][j] = 0.f;

    const float* base = g_qkv + (size_t)b * NSEQ * N_QKV;
    const int n_begin = chunk * ROWS_PER_CHUNK;

    for (int n0 = n_begin; n0 < n_begin + ROWS_PER_CHUNK; n0 += 32) {
        #pragma unroll
        for (int i = 0; i < 2; i++) {
            int id = tid + i * 256;
            int r  = id >> 4;
            int c  = (id & 15) * 4;
            size_t off = (size_t)(n0 + r) * N_QKV + h * DH + c;
            *(float4*)&sk[r][c] = *(const float4*)(base + off + INNER);
            *(float4*)&sv[r][c] = *(const float4*)(base + off + 2 * INNER);
        }
        __syncthreads();

        {
            int r     = tid >> 3;
            int lane8 = tid & 7;
            float vals[8];
            float m = -1e30f;
            #pragma unroll
            for (int j = 0; j < 8; j++) {
                vals[j] = sk[r][lane8 * 8 + j];
                m = fmaxf(m, vals[j]);
            }
            #pragma unroll
            for (int s = 4; s >= 1; s >>= 1)
                m = fmaxf(m, __shfl_xor_sync(0xffffffffu, m, s));
            float sum = 0.f;
            #pragma unroll
            for (int j = 0; j < 8; j++) { vals[j] = __expf(vals[j] - m); sum += vals[j]; }
            #pragma unroll
            for (int s = 4; s >= 1; s >>= 1)
                sum += __shfl_xor_sync(0xffffffffu, sum, s);
            float inv = 1.0f / sum;
            #pragma unroll
            for (int j = 0; j < 8; j++)
                sk[r][lane8 * 8 + j] = vals[j] * inv;
        }
        __syncthreads();

        #pragma unroll 4
        for (int r = 0; r < 32; r++) {
            float4 kd = *(const float4*)&sk[r][d0];
            float4 ve = *(const float4*)&sv[r][e0];
            float kdv[4] = {kd.x, kd.y, kd.z, kd.w};
            float vev[4] = {ve.x, ve.y, ve.z, ve.w};
            #pragma unroll
            for (int i = 0; i < 4; i++)
                #pragma unroll
                for (int j = 0; j < 4; j++)
                    acc[i][j] += kdv[i] * vev[j];
        }
        __syncthreads();
    }

    float* out = g_ctxp + ((size_t)chunk * (B*HEADS) + pair) * DH * DH;
    #pragma unroll
    for (int i = 0; i < 4; i++) {
        float4 v = make_float4(acc[i][0], acc[i][1], acc[i][2], acc[i][3]);
        *(float4*)&out[(d0 + i) * DH + e0] = v;
    }
}

// ---------------------------------------------------------------------------
// Attention-apply; writes g_attn in A-tiled tf32 layout (feeds GEMM4)
// ---------------------------------------------------------------------------
__global__ __launch_bounds__(256) void attn_kernel()
{
    const int pair = blockIdx.x;
    const int b = pair >> 3, h = pair & 7;
    const int n0 = blockIdx.y * 128;
    const int tid = threadIdx.x;

    __shared__ __align__(16) float sctx[DH][DH];
    __shared__ __align__(16) float sq[128][DH];

    for (int idx = tid; idx < DH * DH; idx += 256) {
        float s = 0.f;
        #pragma unroll
        for (int ch = 0; ch < NCHUNK; ch++)
            s += g_ctxp[((size_t)ch * (B*HEADS) + pair) * DH * DH + idx];
        sctx[idx >> 6][idx & 63] = s;
    }

    const float* qbase = g_qkv + (size_t)b * NSEQ * N_QKV + h * DH;
    #pragma unroll
    for (int i = 0; i < 8; i++) {
        int id = tid + i * 256;
        int r  = id >> 4;
        int c  = (id & 15) * 4;
        *(float4*)&sq[r][c] =
            *(const float4*)(qbase + (size_t)(n0 + r) * N_QKV + c);
    }
    __syncthreads();

    const int e0 = (tid & 15) * 4;
    const int rg = tid >> 4;
    float acc[8][4];
    #pragma unroll
    for (int i = 0; i < 8; i++)
        #pragma unroll
        for (int j = 0; j < 4; j++) acc[i][j] = 0.f;

    #pragma unroll 8
    for (int d = 0; d < DH; d++) {
        float4 c4 = *(const float4*)&sctx[d][e0];
        float cv[4] = {c4.x, c4.y, c4.z, c4.w};
        #pragma unroll
        for (int i = 0; i < 8; i++) {
            float a = sq[rg + 16 * i][d];
            #pragma unroll
            for (int j = 0; j < 4; j++)
                acc[i][j] += a * cv[j];
        }
    }

    // tiled store: row = b*NSEQ + n0 + rg + 16*i, col = h*64 + e0 + j
    const int R0 = (b * NSEQ + n0) >> 4;          // + i
    const int S  = (h * DH + e0) >> 3;
    const int g2 = rg & 7;
    const int slot = (rg >> 3) + ((e0 & 4) ? 2 : 0);
    #pragma unroll
    for (int i = 0; i < 8; i++) {
        float* blk = g_attn + ((size_t)(R0 + i) * (INNER >> 3) + S) * 128;
        #pragma unroll
        for (int j = 0; j < 4; j++)
            blk[(g2 * 4 + j) * 4 + slot] = to_tf32(acc[i][j]);
    }
}

// ---------------------------------------------------------------------------
extern "C" void kernel_launch(void* const* d_in, const int* in_sizes, int n_in,
                              void* d_out, int out_size)
{
    const float* x     = (const float*)d_in[0];   // [4,4096,1024]
    const float* w_qkv = (const float*)d_in[1];   // [1536,1024]
    const float* w_out = (const float*)d_in[2];   // [1024,512]
    const float* b_out = (const float*)d_in[3];   // [1024]
    float* out = (float*)d_out;                   // [4,4096,1024]

    float *qkv_p, *attn_p, *xc_p, *wqkvc_p, *woutc_p;
    cudaGetSymbolAddress((void**)&qkv_p,   g_qkv);
    cudaGetSymbolAddress((void**)&attn_p,  g_attn);
    cudaGetSymbolAddress((void**)&xc_p,    g_xc);
    cudaGetSymbolAddress((void**)&wqkvc_p, g_wqkvc);
    cudaGetSymbolAddress((void**)&woutc_p, g_woutc);

    cudaFuncSetAttribute(tf32_gemm_mma,
        cudaFuncAttributeMaxDynamicSharedMemorySize, SMEM_GEMM);

    // 0) tile + round inputs to fragment-native tf32 layouts
    {
        int ta = (M_ROWS / 16) * (DIM / 8) * 32;
        tile_a_kernel<<<(ta + 255) / 256, 256>>>(x, xc_p, M_ROWS, DIM);
        int tb1 = (N_QKV / 8) * (DIM / 8) * 32;
        tile_b_kernel<<<(tb1 + 255) / 256, 256>>>(w_qkv, wqkvc_p, N_QKV, DIM);
        int tb2 = (DIM / 8) * (INNER / 8) * 32;
        tile_b_kernel<<<(tb2 + 255) / 256, 256>>>(w_out, woutc_p, DIM, INNER);
    }

    // 1) QKV projection: [16384,1536] = xc @ wqkvc^T
    tf32_gemm_mma<<<dim3(N_QKV / 256, M_ROWS / 128), 256, SMEM_GEMM>>>(
        xc_p, wqkvc_p, qkv_p, nullptr, M_ROWS, N_QKV, DIM);

    // 2) softmax(k) + context partials
    ctx_kernel<<<dim3(B * HEADS, NCHUNK), 256>>>();

    // 3) q @ context -> attn (tiled tf32) [16384, 512]
    attn_kernel<<<dim3(B * HEADS, NSEQ / 128), 256>>>();

    // 4) output projection + bias: [16384,1024] = attn @ woutc^T + b_out
    tf32_gemm_mma<<<dim3(DIM / 256, M_ROWS / 128), 256, SMEM_GEMM>>>(
        attn_p, woutc_p, out, b_out, M_ROWS, DIM, INNER);
}